// round 7
// baseline (speedup 1.0000x reference)
#include <cuda_runtime.h>
#include <cuda_bf16.h>

#define NN 100000
#define EE 1600000

// Scratch (__device__ globals — no allocation allowed)
__device__ float4 g_t[NN * 8];       // ts = (h @ W) * dinv[row]
__device__ float4 g_h[NN * 8];       // hidden layer activations
__device__ float  g_dinv[NN];
__device__ int    g_deg[NN];
__device__ int    g_rowptr[NN + 1];
__device__ int    g_cur[NN];
__device__ int    g_srcs[EE];        // CSR-by-dst: src ids

// ---------------------------------------------------------------------------
__global__ void k_init(int n) {
    int i = blockIdx.x * blockDim.x + threadIdx.x;
    if (i < n) g_deg[i] = 0;
}

__global__ void k_count(const int* __restrict__ dst, int E) {
    int e = blockIdx.x * blockDim.x + threadIdx.x;
    if (e < E) atomicAdd(&g_deg[dst[e]], 1);
}

// Single-block exclusive scan over g_deg -> g_rowptr / g_cur; dinv = rsqrt(deg+1)
__global__ void k_scan(int n) {
    __shared__ int warp_tot[32];
    __shared__ int s_carry;
    int tid = threadIdx.x;
    int lane = tid & 31, wid = tid >> 5;
    if (tid == 0) s_carry = 0;
    __syncthreads();

    for (int base = 0; base < n; base += 1024) {
        int i = base + tid;
        int v = (i < n) ? g_deg[i] : 0;

        // inclusive warp scan
        int x = v;
#pragma unroll
        for (int o = 1; o < 32; o <<= 1) {
            int y = __shfl_up_sync(0xffffffff, x, o);
            if (lane >= o) x += y;
        }
        if (lane == 31) warp_tot[wid] = x;
        __syncthreads();

        if (wid == 0) {
            int t = warp_tot[lane];
#pragma unroll
            for (int o = 1; o < 32; o <<= 1) {
                int y = __shfl_up_sync(0xffffffff, t, o);
                if (lane >= o) t += y;
            }
            warp_tot[lane] = t;   // inclusive warp totals
        }
        __syncthreads();

        int warp_off = (wid > 0) ? warp_tot[wid - 1] : 0;
        int excl = s_carry + warp_off + (x - v);
        if (i < n) {
            g_rowptr[i] = excl;
            g_cur[i]    = excl;
            g_dinv[i]   = rsqrtf((float)v + 1.0f);  // +1 self loop
        }
        __syncthreads();
        if (tid == 0) s_carry += warp_tot[31];
        __syncthreads();
    }
    if (threadIdx.x == 0) g_rowptr[n] = s_carry;
}

__global__ void k_fill(const int* __restrict__ src,
                       const int* __restrict__ dst, int E) {
    int e = blockIdx.x * blockDim.x + threadIdx.x;
    if (e < E) {
        int d = dst[e];
        int p = atomicAdd(&g_cur[d], 1);
        g_srcs[p] = src[e];
    }
}

// ---------------------------------------------------------------------------
// T[row] = (X[row] @ W) * dinv[row]; packed fma.rn.f32x2, LDS.128 weight reads.
// X == nullptr => read rows from g_h (device-side symbol).
__global__ void k_gemm(const float4* __restrict__ X,
                       const float* __restrict__ Wa,
                       const float* __restrict__ Wb,
                       int n) {
    __shared__ __align__(16) unsigned long long Ws[32][16];
    int tid = threadIdx.x;
    for (int idx = tid; idx < 512; idx += blockDim.x) {
        int k  = idx >> 4;
        int cp = idx & 15;
        int c0 = cp * 2;
        float v0, v1;
        if (Wb == nullptr) {                 // layer 1: W1 [32x32]
            v0 = Wa[k * 32 + c0];
            v1 = Wa[k * 32 + c0 + 1];
        } else if (c0 < 16) {                // layer 2 cols 0-15: Wmu [32x16]
            v0 = Wa[k * 16 + c0];
            v1 = Wa[k * 16 + c0 + 1];
        } else {                             // layer 2 cols 16-31: Wlv [32x16]
            v0 = Wb[k * 16 + (c0 - 16)];
            v1 = Wb[k * 16 + (c0 - 15)];
        }
        unsigned long long p;
        asm("mov.b64 %0, {%1,%2};" : "=l"(p) : "f"(v0), "f"(v1));
        Ws[k][cp] = p;
    }
    __syncthreads();

    int row = blockIdx.x * blockDim.x + tid;
    if (row >= n) return;

    const float4* xr = (X != nullptr) ? (X + (size_t)row * 8)
                                      : (g_h + (size_t)row * 8);
    float x[32];
#pragma unroll
    for (int q = 0; q < 8; q++) {
        float4 v = xr[q];
        x[4 * q + 0] = v.x; x[4 * q + 1] = v.y;
        x[4 * q + 2] = v.z; x[4 * q + 3] = v.w;
    }

    unsigned long long acc[16];
#pragma unroll
    for (int cp = 0; cp < 16; cp++) acc[cp] = 0ull;

#pragma unroll
    for (int k = 0; k < 32; k++) {
        unsigned long long xk;
        asm("mov.b64 %0, {%1,%1};" : "=l"(xk) : "f"(x[k]));
#pragma unroll
        for (int q = 0; q < 8; q++) {       // LDS.128: two u64 per read
            ulonglong2 w = *reinterpret_cast<const ulonglong2*>(&Ws[k][2 * q]);
            asm("fma.rn.f32x2 %0, %1, %2, %0;"
                : "+l"(acc[2 * q]) : "l"(xk), "l"(w.x));
            asm("fma.rn.f32x2 %0, %1, %2, %0;"
                : "+l"(acc[2 * q + 1]) : "l"(xk), "l"(w.y));
        }
    }

    float di = g_dinv[row];
    unsigned long long d2;
    asm("mov.b64 %0, {%1,%1};" : "=l"(d2) : "f"(di));

    float o[32];
#pragma unroll
    for (int cp = 0; cp < 16; cp++) {
        asm("mul.rn.f32x2 %0, %0, %1;" : "+l"(acc[cp]) : "l"(d2));
        asm("mov.b64 {%0,%1}, %2;"
            : "=f"(o[2 * cp]), "=f"(o[2 * cp + 1]) : "l"(acc[cp]));
    }

    float4* tr = g_t + (size_t)row * 8;
#pragma unroll
    for (int q = 0; q < 8; q++)
        tr[q] = make_float4(o[4 * q], o[4 * q + 1], o[4 * q + 2], o[4 * q + 3]);
}

// ---------------------------------------------------------------------------
// CSR gather accumulate: 8 threads per dst node, channel quad c each.
// acc = ts[i] (self loop) + sum_{j in csr(i)} ts[src_j]; 4-way batched for MLP.
__device__ __forceinline__ float4 gather_acc(int i, int c) {
    int beg = g_rowptr[i];
    int end = g_rowptr[i + 1];
    float4 acc = g_t[(size_t)i * 8 + c];   // self loop
    int j = beg;
    for (; j + 4 <= end; j += 4) {
        int s0 = __ldg(&g_srcs[j]);
        int s1 = __ldg(&g_srcs[j + 1]);
        int s2 = __ldg(&g_srcs[j + 2]);
        int s3 = __ldg(&g_srcs[j + 3]);
        float4 v0 = g_t[(size_t)s0 * 8 + c];
        float4 v1 = g_t[(size_t)s1 * 8 + c];
        float4 v2 = g_t[(size_t)s2 * 8 + c];
        float4 v3 = g_t[(size_t)s3 * 8 + c];
        acc.x += v0.x + v1.x + v2.x + v3.x;
        acc.y += v0.y + v1.y + v2.y + v3.y;
        acc.z += v0.z + v1.z + v2.z + v3.z;
        acc.w += v0.w + v1.w + v2.w + v3.w;
    }
    for (; j < end; j++) {
        int s = __ldg(&g_srcs[j]);
        float4 v = g_t[(size_t)s * 8 + c];
        acc.x += v.x; acc.y += v.y; acc.z += v.z; acc.w += v.w;
    }
    return acc;
}

// layer 1: h = relu(dinv * acc + b1) -> g_h
__global__ void k_gather1(const float* __restrict__ b, int n) {
    int gid = blockIdx.x * blockDim.x + threadIdx.x;
    int i = gid >> 3;
    if (i >= n) return;
    int c = gid & 7;
    float4 acc = gather_acc(i, c);
    float di = g_dinv[i];
    float4 bb = ((const float4*)b)[c];
    float4 r;
    r.x = fmaxf(fmaf(di, acc.x, bb.x), 0.f);
    r.y = fmaxf(fmaf(di, acc.y, bb.y), 0.f);
    r.z = fmaxf(fmaf(di, acc.z, bb.z), 0.f);
    r.w = fmaxf(fmaf(di, acc.w, bb.w), 0.f);
    g_h[(size_t)i * 8 + c] = r;
}

// layer 2: mu -> out[0:N*16], logvar -> out[N*16:]
__global__ void k_gather2(const float* __restrict__ bmu,
                          const float* __restrict__ blv,
                          float* __restrict__ out, int n) {
    int gid = blockIdx.x * blockDim.x + threadIdx.x;
    int i = gid >> 3;
    if (i >= n) return;
    int c = gid & 7;
    float4 acc = gather_acc(i, c);
    float di = g_dinv[i];
    float4 r;
    if (c < 4) {
        float4 bb = ((const float4*)bmu)[c];
        r.x = fmaf(di, acc.x, bb.x);
        r.y = fmaf(di, acc.y, bb.y);
        r.z = fmaf(di, acc.z, bb.z);
        r.w = fmaf(di, acc.w, bb.w);
        ((float4*)out)[(size_t)i * 4 + c] = r;
    } else {
        float4 bb = ((const float4*)blv)[c - 4];
        r.x = fmaf(di, acc.x, bb.x);
        r.y = fmaf(di, acc.y, bb.y);
        r.z = fmaf(di, acc.z, bb.z);
        r.w = fmaf(di, acc.w, bb.w);
        ((float4*)(out + (size_t)n * 16))[(size_t)i * 4 + (c - 4)] = r;
    }
}

// ---------------------------------------------------------------------------
extern "C" void kernel_launch(void* const* d_in, const int* in_sizes, int n_in,
                              void* d_out, int out_size) {
    const float* x   = (const float*)d_in[0];
    const int*   ei  = (const int*)d_in[1];
    const float* W1  = (const float*)d_in[2];
    const float* b1  = (const float*)d_in[3];
    const float* Wmu = (const float*)d_in[4];
    const float* bmu = (const float*)d_in[5];
    const float* Wlv = (const float*)d_in[6];
    const float* blv = (const float*)d_in[7];
    float* out = (float*)d_out;

    int N = in_sizes[0] / 32;
    int E = in_sizes[1] / 2;
    const int* src = ei;          // edge_index row 0
    const int* dst = ei + E;      // edge_index row 1

    const int TB = 256;
    int gN   = (N + TB - 1) / TB;
    int gE   = (E + TB - 1) / TB;
    int gN8  = (int)(((long long)N * 8 + TB - 1) / TB);
    int gG   = (N + 127) / 128;   // gemm: 128-thread blocks

    // CSR build (by dst) + dinv
    k_init <<<gN, TB>>>(N);
    k_count<<<gE, TB>>>(dst, E);
    k_scan <<<1, 1024>>>(N);
    k_fill <<<gE, TB>>>(src, dst, E);

    // layer 1
    k_gemm   <<<gG, 128>>>((const float4*)x, W1, nullptr, N);
    k_gather1<<<gN8, TB>>>(b1, N);

    // layer 2 (mu|logvar fused into 32 cols); X=nullptr => read g_h in-kernel
    k_gemm   <<<gG, 128>>>(nullptr, Wmu, Wlv, N);
    k_gather2<<<gN8, TB>>>(bmu, blv, out, N);
}

// round 8
// speedup vs baseline: 1.3886x; 1.3886x over previous
#include <cuda_runtime.h>
#include <cuda_bf16.h>

#define NN 100000
#define EE 1600000

// Scratch (__device__ globals — no allocation allowed)
__device__ float4 g_t[NN * 8];     // ts = (h @ W) * dinv[row]
__device__ float4 g_agg[NN * 8];   // accumulator, seeded with ts (self loop)
__device__ float  g_degf[NN];      // degree (float, includes +1 self loop)

// ---------------------------------------------------------------------------
// deg = 1 (self loop)
__global__ void k_init(int n) {
    int i = blockIdx.x * blockDim.x + threadIdx.x;
    if (i < n) g_degf[i] = 1.0f;
}

// deg count over destinations (plain RED, no return)
__global__ void k_deg(const int* __restrict__ dst, int E) {
    int e = blockIdx.x * blockDim.x + threadIdx.x;
    if (e < E) atomicAdd(&g_degf[dst[e]], 1.0f);
}

// ---------------------------------------------------------------------------
// GEMM: T[row] = (X[row] @ W) * dinv[row], written to BOTH g_t and g_agg
// (g_agg seed = self-loop term).
// 4 threads per row, 8 output cols each (4 packed f32x2 accumulators).
//   Layer 1: X = input x, Wa = W1 [32x32], Wb = null, bias = null.
//   Layer 2: X = null => row input = relu(dinv*g_agg[row] + bias) computed
//            inline (fused post1); Wa = Wmu, Wb = Wlv (16+16 cols).
__global__ void k_gemm(const float4* __restrict__ X,
                       const float* __restrict__ Wa,
                       const float* __restrict__ Wb,
                       const float* __restrict__ bias,
                       int n) {
    __shared__ __align__(16) unsigned long long Ws[32][16];
    __shared__ float bs[32];
    int tid = threadIdx.x;
    for (int idx = tid; idx < 512; idx += blockDim.x) {
        int k  = idx >> 4;
        int cp = idx & 15;
        int c0 = cp * 2;
        float v0, v1;
        if (Wb == nullptr) {                 // layer 1: W1 [32x32]
            v0 = Wa[k * 32 + c0];
            v1 = Wa[k * 32 + c0 + 1];
        } else if (c0 < 16) {                // layer 2 cols 0-15: Wmu [32x16]
            v0 = Wa[k * 16 + c0];
            v1 = Wa[k * 16 + c0 + 1];
        } else {                             // layer 2 cols 16-31: Wlv [32x16]
            v0 = Wb[k * 16 + (c0 - 16)];
            v1 = Wb[k * 16 + (c0 - 15)];
        }
        unsigned long long p;
        asm("mov.b64 %0, {%1,%2};" : "=l"(p) : "f"(v0), "f"(v1));
        Ws[k][cp] = p;
    }
    if (tid < 32) bs[tid] = (bias != nullptr) ? bias[tid] : 0.0f;
    __syncthreads();

    int gid = blockIdx.x * blockDim.x + tid;
    int row = gid >> 2;
    int cg  = gid & 3;                       // column group: cols 8cg..8cg+7
    if (row >= n) return;

    float di = rsqrtf(g_degf[row]);

    const float4* xr = (X != nullptr) ? (X + (size_t)row * 8)
                                      : (g_agg + (size_t)row * 8);
    float x[32];
#pragma unroll
    for (int q = 0; q < 8; q++) {
        float4 v = xr[q];
        x[4 * q + 0] = v.x; x[4 * q + 1] = v.y;
        x[4 * q + 2] = v.z; x[4 * q + 3] = v.w;
    }
    if (X == nullptr) {                      // fused post1: relu(di*agg + b1)
#pragma unroll
        for (int j = 0; j < 32; j++)
            x[j] = fmaxf(fmaf(di, x[j], bs[j]), 0.0f);
    }

    unsigned long long acc[4];
#pragma unroll
    for (int j = 0; j < 4; j++) acc[j] = 0ull;

    int cpb = cg * 4;
#pragma unroll
    for (int k = 0; k < 32; k++) {
        unsigned long long xk;
        asm("mov.b64 %0, {%1,%1};" : "=l"(xk) : "f"(x[k]));
        ulonglong2 w0 = *reinterpret_cast<const ulonglong2*>(&Ws[k][cpb]);
        ulonglong2 w1 = *reinterpret_cast<const ulonglong2*>(&Ws[k][cpb + 2]);
        asm("fma.rn.f32x2 %0, %1, %2, %0;" : "+l"(acc[0]) : "l"(xk), "l"(w0.x));
        asm("fma.rn.f32x2 %0, %1, %2, %0;" : "+l"(acc[1]) : "l"(xk), "l"(w0.y));
        asm("fma.rn.f32x2 %0, %1, %2, %0;" : "+l"(acc[2]) : "l"(xk), "l"(w1.x));
        asm("fma.rn.f32x2 %0, %1, %2, %0;" : "+l"(acc[3]) : "l"(xk), "l"(w1.y));
    }

    unsigned long long d2;
    asm("mov.b64 %0, {%1,%1};" : "=l"(d2) : "f"(di));
    float o[8];
#pragma unroll
    for (int j = 0; j < 4; j++) {
        asm("mul.rn.f32x2 %0, %0, %1;" : "+l"(acc[j]) : "l"(d2));
        asm("mov.b64 {%0,%1}, %2;"
            : "=f"(o[2 * j]), "=f"(o[2 * j + 1]) : "l"(acc[j]));
    }

    float4 r0 = make_float4(o[0], o[1], o[2], o[3]);
    float4 r1 = make_float4(o[4], o[5], o[6], o[7]);
    size_t base = (size_t)row * 8 + cg * 2;
    g_t[base]       = r0;
    g_t[base + 1]   = r1;
    g_agg[base]     = r0;   // self-loop seed
    g_agg[base + 1] = r1;
}

// ---------------------------------------------------------------------------
// AGG[dst] += T[src]; 8 threads/edge; float4 gather + vector reduction
__global__ void k_scatter(const int* __restrict__ src,
                          const int* __restrict__ dst, int E) {
    int gid = blockIdx.x * blockDim.x + threadIdx.x;
    int e = gid >> 3;
    if (e >= E) return;
    int c = gid & 7;
    int s = __ldg(&src[e]);
    int d = __ldg(&dst[e]);
    float4 v = g_t[(size_t)s * 8 + c];
    float4* p = g_agg + (size_t)d * 8 + c;
    asm volatile("red.global.add.v4.f32 [%0], {%1,%2,%3,%4};"
                 :: "l"(p), "f"(v.x), "f"(v.y), "f"(v.z), "f"(v.w)
                 : "memory");
}

// ---------------------------------------------------------------------------
// final: mu -> out[0:N*16], logvar -> out[N*16:]
// out = dinv * agg + bias   (agg already contains self-loop term)
__global__ void k_post2(const float* __restrict__ bmu,
                        const float* __restrict__ blv,
                        float* __restrict__ out, int n) {
    int gid = blockIdx.x * blockDim.x + threadIdx.x;
    int i = gid >> 3;
    if (i >= n) return;
    int c = gid & 7;
    float di = rsqrtf(g_degf[i]);
    float4 a = g_agg[(size_t)i * 8 + c];
    float4 r;
    if (c < 4) {
        float4 bb = ((const float4*)bmu)[c];
        r.x = fmaf(di, a.x, bb.x);
        r.y = fmaf(di, a.y, bb.y);
        r.z = fmaf(di, a.z, bb.z);
        r.w = fmaf(di, a.w, bb.w);
        ((float4*)out)[(size_t)i * 4 + c] = r;
    } else {
        float4 bb = ((const float4*)blv)[c - 4];
        r.x = fmaf(di, a.x, bb.x);
        r.y = fmaf(di, a.y, bb.y);
        r.z = fmaf(di, a.z, bb.z);
        r.w = fmaf(di, a.w, bb.w);
        ((float4*)(out + (size_t)n * 16))[(size_t)i * 4 + (c - 4)] = r;
    }
}

// ---------------------------------------------------------------------------
extern "C" void kernel_launch(void* const* d_in, const int* in_sizes, int n_in,
                              void* d_out, int out_size) {
    const float* x   = (const float*)d_in[0];
    const int*   ei  = (const int*)d_in[1];
    const float* W1  = (const float*)d_in[2];
    const float* b1  = (const float*)d_in[3];
    const float* Wmu = (const float*)d_in[4];
    const float* bmu = (const float*)d_in[5];
    const float* Wlv = (const float*)d_in[6];
    const float* blv = (const float*)d_in[7];
    float* out = (float*)d_out;

    int N = in_sizes[0] / 32;
    int E = in_sizes[1] / 2;
    const int* src = ei;          // edge_index row 0
    const int* dst = ei + E;      // edge_index row 1

    const int TB = 256;
    int gN  = (N + TB - 1) / TB;
    int gE  = (E + TB - 1) / TB;
    int gN4 = (int)(((long long)N * 4 + TB - 1) / TB);   // gemm: 4 thr/row
    int gN8 = (int)(((long long)N * 8 + TB - 1) / TB);
    int gE8 = (int)(((long long)E * 8 + TB - 1) / TB);

    // degrees (dinv computed inline via rsqrtf where needed)
    k_init<<<gN, TB>>>(N);
    k_deg <<<gE, TB>>>(dst, E);

    // layer 1: t1 -> g_t, g_agg (seeded); scatter adds neighbor terms
    k_gemm   <<<gN4, TB>>>((const float4*)x, W1, nullptr, nullptr, N);
    k_scatter<<<gE8, TB>>>(src, dst, E);

    // layer 2: fused relu(dinv*agg + b1) -> GEMM(mu|lv) -> re-seed agg
    k_gemm   <<<gN4, TB>>>(nullptr, Wmu, Wlv, b1, N);
    k_scatter<<<gE8, TB>>>(src, dst, E);

    // final bias + dinv scale, split mu / logvar
    k_post2<<<gN8, TB>>>(bmu, blv, out, N);
}

// round 9
// speedup vs baseline: 1.4660x; 1.0557x over previous
#include <cuda_runtime.h>
#include <cuda_bf16.h>

#define NN 100000
#define EE 1600000

// Scratch (__device__ globals — no allocation allowed)
__device__ float4 g_t[NN * 8];     // ts = (h @ W) * dinv[row]
__device__ float4 g_agg[NN * 8];   // accumulator, seeded with ts (self loop)
__device__ float  g_degf[NN];      // degree (float, includes +1 self loop)

// ---------------------------------------------------------------------------
// deg = 1 (self loop)
__global__ void k_init(int n) {
    int i = blockIdx.x * blockDim.x + threadIdx.x;
    if (i < n) g_degf[i] = 1.0f;
}

// deg count over destinations (plain RED, no return)
__global__ void k_deg(const int* __restrict__ dst, int E) {
    int e = blockIdx.x * blockDim.x + threadIdx.x;
    if (e < E) atomicAdd(&g_degf[dst[e]], 1.0f);
}

// ---------------------------------------------------------------------------
// GEMM: T[row] = (X[row] @ W) * dinv[row], written to BOTH g_t and g_agg
// (g_agg seed = self-loop term).
// 4 threads per row, 8 output cols each (4 packed f32x2 accumulators).
//   Layer 1: X = input x, Wa = W1 [32x32], Wb = null, bias = null.
//   Layer 2: X = null => row input = relu(dinv*g_agg[row] + bias) computed
//            inline (fused post1); Wa = Wmu, Wb = Wlv (16+16 cols).
__global__ void k_gemm(const float4* __restrict__ X,
                       const float* __restrict__ Wa,
                       const float* __restrict__ Wb,
                       const float* __restrict__ bias,
                       int n) {
    __shared__ __align__(16) unsigned long long Ws[32][16];
    __shared__ float bs[32];
    int tid = threadIdx.x;
    for (int idx = tid; idx < 512; idx += blockDim.x) {
        int k  = idx >> 4;
        int cp = idx & 15;
        int c0 = cp * 2;
        float v0, v1;
        if (Wb == nullptr) {                 // layer 1: W1 [32x32]
            v0 = Wa[k * 32 + c0];
            v1 = Wa[k * 32 + c0 + 1];
        } else if (c0 < 16) {                // layer 2 cols 0-15: Wmu [32x16]
            v0 = Wa[k * 16 + c0];
            v1 = Wa[k * 16 + c0 + 1];
        } else {                             // layer 2 cols 16-31: Wlv [32x16]
            v0 = Wb[k * 16 + (c0 - 16)];
            v1 = Wb[k * 16 + (c0 - 15)];
        }
        unsigned long long p;
        asm("mov.b64 %0, {%1,%2};" : "=l"(p) : "f"(v0), "f"(v1));
        Ws[k][cp] = p;
    }
    if (tid < 32) bs[tid] = (bias != nullptr) ? bias[tid] : 0.0f;
    __syncthreads();

    int gid = blockIdx.x * blockDim.x + tid;
    int row = gid >> 2;
    int cg  = gid & 3;                       // column group: cols 8cg..8cg+7
    if (row >= n) return;

    float di = rsqrtf(g_degf[row]);

    const float4* xr = (X != nullptr) ? (X + (size_t)row * 8)
                                      : (g_agg + (size_t)row * 8);
    float x[32];
#pragma unroll
    for (int q = 0; q < 8; q++) {
        float4 v = xr[q];
        x[4 * q + 0] = v.x; x[4 * q + 1] = v.y;
        x[4 * q + 2] = v.z; x[4 * q + 3] = v.w;
    }
    if (X == nullptr) {                      // fused post1: relu(di*agg + b1)
#pragma unroll
        for (int j = 0; j < 32; j++)
            x[j] = fmaxf(fmaf(di, x[j], bs[j]), 0.0f);
    }

    unsigned long long acc[4];
#pragma unroll
    for (int j = 0; j < 4; j++) acc[j] = 0ull;

    int cpb = cg * 4;
#pragma unroll
    for (int k = 0; k < 32; k++) {
        unsigned long long xk;
        asm("mov.b64 %0, {%1,%1};" : "=l"(xk) : "f"(x[k]));
        ulonglong2 w0 = *reinterpret_cast<const ulonglong2*>(&Ws[k][cpb]);
        ulonglong2 w1 = *reinterpret_cast<const ulonglong2*>(&Ws[k][cpb + 2]);
        asm("fma.rn.f32x2 %0, %1, %2, %0;" : "+l"(acc[0]) : "l"(xk), "l"(w0.x));
        asm("fma.rn.f32x2 %0, %1, %2, %0;" : "+l"(acc[1]) : "l"(xk), "l"(w0.y));
        asm("fma.rn.f32x2 %0, %1, %2, %0;" : "+l"(acc[2]) : "l"(xk), "l"(w1.x));
        asm("fma.rn.f32x2 %0, %1, %2, %0;" : "+l"(acc[3]) : "l"(xk), "l"(w1.y));
    }

    unsigned long long d2;
    asm("mov.b64 %0, {%1,%1};" : "=l"(d2) : "f"(di));
    float o[8];
#pragma unroll
    for (int j = 0; j < 4; j++) {
        asm("mul.rn.f32x2 %0, %0, %1;" : "+l"(acc[j]) : "l"(d2));
        asm("mov.b64 {%0,%1}, %2;"
            : "=f"(o[2 * j]), "=f"(o[2 * j + 1]) : "l"(acc[j]));
    }

    float4 r0 = make_float4(o[0], o[1], o[2], o[3]);
    float4 r1 = make_float4(o[4], o[5], o[6], o[7]);
    size_t base = (size_t)row * 8 + cg * 2;
    g_t[base]       = r0;
    g_t[base + 1]   = r1;
    g_agg[base]     = r0;   // self-loop seed
    g_agg[base + 1] = r1;
}

// ---------------------------------------------------------------------------
// AGG[dst] += T[src].
// Each warp owns 32 edges: indices front-loaded into registers (2 coalesced
// LDG wavefronts per 32 edges, was 2 per 4 edges), distributed via SHFL
// (no L1tex wavefront cost). 8 independent iterations x 4 edges x 8 lanes:
// lanes 8k..8k+7 cover one edge's full 128B row (coalesced gather + RED.128).
__global__ void k_scatter(const int* __restrict__ src,
                          const int* __restrict__ dst, int E) {
    int warp = (blockIdx.x * blockDim.x + threadIdx.x) >> 5;
    int lane = threadIdx.x & 31;
    int base = warp * 32;
    if (base >= E) return;

    int e = base + lane;
    int sreg = (e < E) ? __ldg(&src[e]) : 0;
    int dreg = (e < E) ? __ldg(&dst[e]) : 0;

    int c   = lane & 7;      // channel quad within row
    int sub = lane >> 3;     // which of 4 edges this iteration

    if (base + 32 <= E) {
#pragma unroll
        for (int it = 0; it < 8; it++) {
            int eloc = it * 4 + sub;
            int s = __shfl_sync(0xffffffff, sreg, eloc);
            int d = __shfl_sync(0xffffffff, dreg, eloc);
            float4 v = g_t[(size_t)s * 8 + c];
            float4* p = g_agg + (size_t)d * 8 + c;
            asm volatile("red.global.add.v4.f32 [%0], {%1,%2,%3,%4};"
                         :: "l"(p), "f"(v.x), "f"(v.y), "f"(v.z), "f"(v.w)
                         : "memory");
        }
    } else {
#pragma unroll
        for (int it = 0; it < 8; it++) {
            int eloc = it * 4 + sub;
            int s = __shfl_sync(0xffffffff, sreg, eloc);
            int d = __shfl_sync(0xffffffff, dreg, eloc);
            if (base + eloc < E) {
                float4 v = g_t[(size_t)s * 8 + c];
                float4* p = g_agg + (size_t)d * 8 + c;
                asm volatile("red.global.add.v4.f32 [%0], {%1,%2,%3,%4};"
                             :: "l"(p), "f"(v.x), "f"(v.y), "f"(v.z), "f"(v.w)
                             : "memory");
            }
        }
    }
}

// ---------------------------------------------------------------------------
// final: mu -> out[0:N*16], logvar -> out[N*16:]
// out = dinv * agg + bias   (agg already contains self-loop term)
__global__ void k_post2(const float* __restrict__ bmu,
                        const float* __restrict__ blv,
                        float* __restrict__ out, int n) {
    int gid = blockIdx.x * blockDim.x + threadIdx.x;
    int i = gid >> 3;
    if (i >= n) return;
    int c = gid & 7;
    float di = rsqrtf(g_degf[i]);
    float4 a = g_agg[(size_t)i * 8 + c];
    float4 r;
    if (c < 4) {
        float4 bb = ((const float4*)bmu)[c];
        r.x = fmaf(di, a.x, bb.x);
        r.y = fmaf(di, a.y, bb.y);
        r.z = fmaf(di, a.z, bb.z);
        r.w = fmaf(di, a.w, bb.w);
        ((float4*)out)[(size_t)i * 4 + c] = r;
    } else {
        float4 bb = ((const float4*)blv)[c - 4];
        r.x = fmaf(di, a.x, bb.x);
        r.y = fmaf(di, a.y, bb.y);
        r.z = fmaf(di, a.z, bb.z);
        r.w = fmaf(di, a.w, bb.w);
        ((float4*)(out + (size_t)n * 16))[(size_t)i * 4 + (c - 4)] = r;
    }
}

// ---------------------------------------------------------------------------
extern "C" void kernel_launch(void* const* d_in, const int* in_sizes, int n_in,
                              void* d_out, int out_size) {
    const float* x   = (const float*)d_in[0];
    const int*   ei  = (const int*)d_in[1];
    const float* W1  = (const float*)d_in[2];
    const float* b1  = (const float*)d_in[3];
    const float* Wmu = (const float*)d_in[4];
    const float* bmu = (const float*)d_in[5];
    const float* Wlv = (const float*)d_in[6];
    const float* blv = (const float*)d_in[7];
    float* out = (float*)d_out;

    int N = in_sizes[0] / 32;
    int E = in_sizes[1] / 2;
    const int* src = ei;          // edge_index row 0
    const int* dst = ei + E;      // edge_index row 1

    const int TB = 256;
    int gN  = (N + TB - 1) / TB;
    int gE  = (E + TB - 1) / TB;
    int gN4 = (int)(((long long)N * 4 + TB - 1) / TB);   // gemm: 4 thr/row
    int gN8 = (int)(((long long)N * 8 + TB - 1) / TB);
    int gEw = (int)(((long long)E + TB - 1) / TB);       // 1 thread per edge
                                                         // (32 edges per warp)

    // degrees (dinv computed inline via rsqrtf where needed)
    k_init<<<gN, TB>>>(N);
    k_deg <<<gE, TB>>>(dst, E);

    // layer 1: t1 -> g_t, g_agg (seeded); scatter adds neighbor terms
    k_gemm   <<<gN4, TB>>>((const float4*)x, W1, nullptr, nullptr, N);
    k_scatter<<<gEw, TB>>>(src, dst, E);

    // layer 2: fused relu(dinv*agg + b1) -> GEMM(mu|lv) -> re-seed agg
    k_gemm   <<<gN4, TB>>>(nullptr, Wmu, Wlv, b1, N);
    k_scatter<<<gEw, TB>>>(src, dst, E);

    // final bias + dinv scale, split mu / logvar
    k_post2<<<gN8, TB>>>(bmu, blv, out, N);
}